// round 1
// baseline (speedup 1.0000x reference)
#include <cuda_runtime.h>

// Problem constants (fixed shapes from reference: n=2, c=64, s=4, h=64, w=44)
#define N_  2
#define C_  64
#define S_  4
#define H_  64
#define W_  44
#define B_  (N_ * S_)          // 8 effective batches
#define P_  (H_ * W_)          // 2816 pixels
#define R_  3                  // window radius
#define KT  49                 // taps

#define TH  4                  // tile height (pixels per block in y)
#define CC  8                  // channels staged per chunk
#define HALO_H (TH + 2 * R_)   // 10 shared rows
#define SW  (W_ + 2 * R_)      // 50 shared cols (x halo zero-padded)

// One thread per output pixel. Block = (W_, TH) = 176 threads.
// Grid = B_ * (H_/TH) = 128 blocks (~1 per SM, single wave).
__global__ __launch_bounds__(W_ * TH)
void corr_flow_kernel(const float* __restrict__ f0g,
                      const float* __restrict__ f1g,
                      float* __restrict__ out) {
    __shared__ float f1s[CC][HALO_H][SW];   // 16000 B
    __shared__ float f0s[CC][TH][W_];       //  5632 B

    const int tx = threadIdx.x;             // 0..43 (x)
    const int ty = threadIdx.y;             // 0..3  (tile row)
    const int tid = ty * W_ + tx;
    const int nthreads = W_ * TH;

    const int blk   = blockIdx.x;           // 0..127
    const int b     = blk >> 4;             // 0..7
    const int ytile = blk & 15;
    const int y0    = ytile * TH;
    const int n_idx = b / S_;
    const int s_idx = b - n_idx * S_;

    // 49 correlation accumulators in registers
    float corr[KT];
#pragma unroll
    for (int k = 0; k < KT; k++) corr[k] = 0.f;

    // Zero the whole f1 halo buffer once: x-halo columns and out-of-image rows
    // stay zero for the whole kernel; in-image entries are overwritten each chunk.
    {
        float* p = &f1s[0][0][0];
        for (int i = tid; i < CC * HALO_H * SW; i += nthreads) p[i] = 0.f;
    }
    __syncthreads();

    // Base global offset for (n_idx, ch=0, s_idx): element stride per channel = S_*P_
    const long base = ((long)n_idx * C_ * S_ + s_idx) * (long)P_;

    for (int ch0 = 0; ch0 < C_; ch0 += CC) {
        // ---- stage f1 chunk: CC channels x HALO_H rows x W_ cols (coalesced in x)
        for (int i = tid; i < CC * HALO_H * W_; i += nthreads) {
            int cc  = i / (HALO_H * W_);
            int rem = i - cc * (HALO_H * W_);
            int r   = rem / W_;
            int x   = rem - r * W_;
            int gy  = y0 - R_ + r;
            float v = 0.f;
            if (gy >= 0 && gy < H_) {
                v = f1g[base + (long)(ch0 + cc) * (S_ * P_) + gy * W_ + x];
            }
            f1s[cc][r][x + R_] = v;
        }
        // ---- stage f0 chunk: CC x TH x W_
        for (int i = tid; i < CC * TH * W_; i += nthreads) {
            int cc  = i / (TH * W_);
            int rem = i - cc * (TH * W_);
            int r   = rem / W_;
            int x   = rem - r * W_;
            f0s[cc][r][x] = f0g[base + (long)(ch0 + cc) * (S_ * P_) + (y0 + r) * W_ + x];
        }
        __syncthreads();

        // ---- accumulate 49 taps over this channel chunk
#pragma unroll 2
        for (int cc = 0; cc < CC; cc++) {
            float a = f0s[cc][ty][tx];
#pragma unroll
            for (int dy = 0; dy < 7; dy++) {
#pragma unroll
                for (int dx = 0; dx < 7; dx++) {
                    // shared row r = ty + dy (global y0+ty+dy-3 maps to r),
                    // shared col = tx + dx (x halo offset +3 already applied)
                    corr[dy * 7 + dx] = fmaf(a, f1s[cc][ty + dy][tx + dx],
                                             corr[dy * 7 + dx]);
                }
            }
        }
        __syncthreads();
    }

    // ---- epilogue: masked softmax over 49 taps, expected offset = flow
    const int x = tx;
    const int y = y0 + ty;
    const float scale = 0.125f;   // 1/sqrt(64)

    float m = -1e30f;
#pragma unroll
    for (int dy = 0; dy < 7; dy++) {
#pragma unroll
        for (int dx = 0; dx < 7; dx++) {
            int gx = x + dx - R_;
            int gy = y + dy - R_;
            if (gx >= 0 && gx < W_ && gy >= 0 && gy < H_) {
                float c = corr[dy * 7 + dx] * scale;
                m = fmaxf(m, c);
            }
        }
    }

    float se = 0.f, sx = 0.f, sy = 0.f;
#pragma unroll
    for (int dy = 0; dy < 7; dy++) {
#pragma unroll
        for (int dx = 0; dx < 7; dx++) {
            int gx = x + dx - R_;
            int gy = y + dy - R_;
            if (gx >= 0 && gx < W_ && gy >= 0 && gy < H_) {
                float e = __expf(corr[dy * 7 + dx] * scale - m);
                se += e;
                sx += e * (float)(dx - R_);
                sy += e * (float)(dy - R_);
            }
        }
    }
    float inv = 1.0f / se;

    // out layout (n, 2, s, h, w)
    int ob = ((n_idx * 2) * S_ + s_idx) * P_ + y * W_ + x;
    out[ob]           = sx * inv;           // flow x (channel 0)
    out[ob + S_ * P_] = sy * inv;           // flow y (channel 1)
}

extern "C" void kernel_launch(void* const* d_in, const int* in_sizes, int n_in,
                              void* d_out, int out_size) {
    const float* f0 = (const float*)d_in[0];
    const float* f1 = (const float*)d_in[1];
    float* out = (float*)d_out;
    dim3 block(W_, TH);
    dim3 grid(B_ * (H_ / TH));   // 128 blocks
    corr_flow_kernel<<<grid, block>>>(f0, f1, out);
}

// round 3
// speedup vs baseline: 1.3696x; 1.3696x over previous
#include <cuda_runtime.h>

// Fixed shapes: n=2, c=64, s=4, h=64, w=44
#define N_  2
#define C_  64
#define S_  4
#define H_  64
#define W_  44
#define B_  (N_ * S_)          // 8 effective batches
#define P_  (H_ * W_)          // 2816 pixels
#define R_  3
#define KT  49

#define TH  4                  // tile rows per block
#define CC  8                  // channels staged per chunk
#define G_  4                  // threads (tap-groups) per pixel
#define NTAP 13                // max taps per group (g==0 has 13, others 12)
#define HALO_H (TH + 2 * R_)   // 10 shared rows
#define SW  52                 // 50 used cols + 2 pad (row stride, mod32=20)
#define NTHREADS (W_ * TH * G_)  // 704

__global__ __launch_bounds__(NTHREADS, 1)
void corr_flow_kernel(const float* __restrict__ f0g,
                      const float* __restrict__ f1g,
                      float* __restrict__ out) {
    __shared__ float f1s[CC][HALO_H][SW];   // 8*10*52*4 = 16640 B
    __shared__ float f0s[CC][TH][W_];       // 8*4*44*4  =  5632 B

    const int tid = threadIdx.x;
    const int g   = tid & (G_ - 1);         // tap group 0..3
    const int p   = tid >> 2;               // pixel within tile 0..175
    const int tx  = p % W_;
    const int ty  = p / W_;

    const int blk   = blockIdx.x;           // 0..127
    const int b     = blk >> 4;             // 0..7
    const int ytile = blk & 15;
    const int y0    = ytile * TH;
    const int n_idx = b / S_;
    const int s_idx = b - n_idx * S_;

    // Per-thread tap offsets within the shared f1 plane: tap t = g + 4*i
    int off[NTAP];
#pragma unroll
    for (int i = 0; i < NTAP; i++) {
        int t = g + G_ * i;
        if (t > 48) t = 48;                 // clamp (masked out later)
        off[i] = (t / 7) * SW + (t % 7);
    }

    float acc[NTAP];
#pragma unroll
    for (int i = 0; i < NTAP; i++) acc[i] = 0.f;

    // Zero f1 halo buffer once (x-halo cols & out-of-image rows stay zero)
    {
        float* zp = &f1s[0][0][0];
        for (int i = tid; i < CC * HALO_H * SW; i += NTHREADS) zp[i] = 0.f;
    }
    __syncthreads();

    const long base = ((long)n_idx * C_ * S_ + s_idx) * (long)P_;
    const float* f1base = &f1s[0][0][0] + ty * SW + tx;   // +dy*SW+dx added via off[]
    const int last = (g == 0) ? NTAP : (NTAP - 1);

    for (int ch0 = 0; ch0 < C_; ch0 += CC) {
        // ---- stage f1 chunk: CC channels x HALO_H rows x W_ cols (store at x+R_)
        for (int i = tid; i < CC * HALO_H * W_; i += NTHREADS) {
            int cc  = i / (HALO_H * W_);
            int rem = i - cc * (HALO_H * W_);
            int r   = rem / W_;
            int x   = rem - r * W_;
            int gy  = y0 - R_ + r;
            float v = 0.f;
            if (gy >= 0 && gy < H_) {
                v = f1g[base + (long)(ch0 + cc) * (S_ * P_) + gy * W_ + x];
            }
            f1s[cc][r][x + R_] = v;
        }
        // ---- stage f0 chunk
        for (int i = tid; i < CC * TH * W_; i += NTHREADS) {
            int cc  = i / (TH * W_);
            int rem = i - cc * (TH * W_);
            int r   = rem / W_;
            int x   = rem - r * W_;
            f0s[cc][r][x] = f0g[base + (long)(ch0 + cc) * (S_ * P_) + (y0 + r) * W_ + x];
        }
        __syncthreads();

        // ---- accumulate this thread's taps over CC channels
#pragma unroll
        for (int cc = 0; cc < CC; cc++) {
            float a = f0s[cc][ty][tx];               // broadcast across 4 group lanes
            const float* fp = f1base + cc * (HALO_H * SW);
#pragma unroll
            for (int i = 0; i < NTAP; i++) {
                if (i < last) acc[i] = fmaf(a, fp[off[i]], acc[i]);
            }
        }
        __syncthreads();
    }

    // ---- epilogue: masked softmax over taps, split across 4 lanes
    const int x = tx;
    const int y = y0 + ty;
    const float scale = 0.125f;   // 1/sqrt(64)

    float m = -1e30f;
#pragma unroll
    for (int i = 0; i < NTAP; i++) {
        int t = g + G_ * i;
        if (t < KT) {
            int dx = t % 7 - R_;
            int dy = t / 7 - R_;
            int gx = x + dx, gy = y + dy;
            if (gx >= 0 && gx < W_ && gy >= 0 && gy < H_) {
                m = fmaxf(m, acc[i] * scale);
            }
        }
    }
    // max over the 4 group lanes (adjacent lanes)
    m = fmaxf(m, __shfl_xor_sync(0xffffffffu, m, 1));
    m = fmaxf(m, __shfl_xor_sync(0xffffffffu, m, 2));

    float se = 0.f, sx = 0.f, sy = 0.f;
#pragma unroll
    for (int i = 0; i < NTAP; i++) {
        int t = g + G_ * i;
        if (t < KT) {
            int dx = t % 7 - R_;
            int dy = t / 7 - R_;
            int gx = x + dx, gy = y + dy;
            if (gx >= 0 && gx < W_ && gy >= 0 && gy < H_) {
                float e = __expf(acc[i] * scale - m);
                se += e;
                sx += e * (float)dx;
                sy += e * (float)dy;
            }
        }
    }
    se += __shfl_xor_sync(0xffffffffu, se, 1);
    se += __shfl_xor_sync(0xffffffffu, se, 2);
    sx += __shfl_xor_sync(0xffffffffu, sx, 1);
    sx += __shfl_xor_sync(0xffffffffu, sx, 2);
    sy += __shfl_xor_sync(0xffffffffu, sy, 1);
    sy += __shfl_xor_sync(0xffffffffu, sy, 2);

    if (g == 0) {
        float inv = 1.0f / se;
        int ob = ((n_idx * 2) * S_ + s_idx) * P_ + y * W_ + x;
        out[ob]           = sx * inv;   // flow x
        out[ob + S_ * P_] = sy * inv;   // flow y
    }
}

extern "C" void kernel_launch(void* const* d_in, const int* in_sizes, int n_in,
                              void* d_out, int out_size) {
    const float* f0 = (const float*)d_in[0];
    const float* f1 = (const float*)d_in[1];
    float* out = (float*)d_out;
    corr_flow_kernel<<<B_ * (H_ / TH), NTHREADS>>>(f0, f1, out);
}

// round 4
// speedup vs baseline: 2.1725x; 1.5863x over previous
#include <cuda_runtime.h>

// Fixed shapes: n=2, c=64, s=4, h=64, w=44
#define N_  2
#define C_  64
#define S_  4
#define H_  64
#define W_  44
#define B_  (N_ * S_)            // 8 effective batches
#define P_  (H_ * W_)            // 2816 pixels
#define R_  3
#define KT  49

#define TH  4                    // tile rows per block
#define CC  8                    // channels staged per chunk
#define NCH (C_ / CC)            // 8 chunks
#define G_  4                    // threads (tap-groups) per pixel
#define NTAP 13                  // max taps per group
#define HALO_H (TH + 2 * R_)     // 10 shared rows
#define SW  52                   // 50 used cols + 2 pad
#define NTHREADS (W_ * TH * G_)  // 704

#define F1_CHUNK (CC * HALO_H * W_)   // 3520 = 704 * 5
#define F0_CHUNK (CC * TH * W_)       // 1408 = 704 * 2
#define NF1 5
#define NF0 2
#define CHSTRIDE (S_ * P_)            // per-channel element stride

__global__ __launch_bounds__(NTHREADS, 1)
void corr_flow_kernel(const float* __restrict__ f0g,
                      const float* __restrict__ f1g,
                      float* __restrict__ out) {
    __shared__ float f1s[2][CC][HALO_H][SW];   // 2 * 16640 B
    __shared__ float f0s[2][CC][TH][W_];       // 2 *  5632 B

    const int tid = threadIdx.x;
    const int g   = tid & (G_ - 1);
    const int p   = tid >> 2;
    const int tx  = p % W_;
    const int ty  = p / W_;

    const int blk   = blockIdx.x;
    const int b     = blk >> 4;
    const int ytile = blk & 15;
    const int y0    = ytile * TH;
    const int n_idx = b / S_;
    const int s_idx = b - n_idx * S_;

    const int base = (n_idx * C_ * S_ + s_idx) * P_;   // fits in int

    // ---- precompute staging maps (chunk-invariant) ----
    int f1_s[NF1];   // smem linear offset within one f1 buffer
    int f1_g[NF1];   // global offset (ch0=0), or -1 if out-of-image row
#pragma unroll
    for (int k = 0; k < NF1; k++) {
        int i   = tid + k * NTHREADS;
        int cc  = i / (HALO_H * W_);
        int rem = i - cc * (HALO_H * W_);
        int r   = rem / W_;
        int x   = rem - r * W_;
        int gy  = y0 - R_ + r;
        f1_s[k] = cc * (HALO_H * SW) + r * SW + x + R_;
        f1_g[k] = (gy >= 0 && gy < H_) ? (base + cc * CHSTRIDE + gy * W_ + x) : -1;
    }
    int f0_s[NF0];
    int f0_g[NF0];
#pragma unroll
    for (int k = 0; k < NF0; k++) {
        int i   = tid + k * NTHREADS;
        int cc  = i / (TH * W_);
        int rem = i - cc * (TH * W_);
        int r   = rem / W_;
        int x   = rem - r * W_;
        f0_s[k] = i;   // f0 buffer is dense, linear
        f0_g[k] = base + cc * CHSTRIDE + (y0 + r) * W_ + x;
    }

    // per-thread tap offsets within shared f1 plane: tap t = g + 4*i
    int off[NTAP];
#pragma unroll
    for (int i = 0; i < NTAP; i++) {
        int t = g + G_ * i;
        if (t > 48) t = 48;
        off[i] = (t / 7) * SW + (t % 7);
    }
    float acc[NTAP];
#pragma unroll
    for (int i = 0; i < NTAP; i++) acc[i] = 0.f;

    // zero halo regions of both f1 buffers once
    {
        float* zp = &f1s[0][0][0][0];
        for (int i = tid; i < 2 * CC * HALO_H * SW; i += NTHREADS) zp[i] = 0.f;
    }

    const int last = (g == 0) ? NTAP : (NTAP - 1);

    // ---- prologue: prefetch chunk 0, store to buffer 0 ----
    float r1[NF1], r0[NF0];
#pragma unroll
    for (int k = 0; k < NF1; k++) r1[k] = (f1_g[k] >= 0) ? f1g[f1_g[k]] : 0.f;
#pragma unroll
    for (int k = 0; k < NF0; k++) r0[k] = f0g[f0_g[k]];

    float* f1buf0 = &f1s[0][0][0][0];
    float* f0buf0 = &f0s[0][0][0][0];
    float* f1buf1 = &f1s[1][0][0][0];
    float* f0buf1 = &f0s[1][0][0][0];

#pragma unroll
    for (int k = 0; k < NF1; k++) f1buf0[f1_s[k]] = r1[k];
#pragma unroll
    for (int k = 0; k < NF0; k++) f0buf0[f0_s[k]] = r0[k];
    __syncthreads();

    // ---- pipelined mainloop ----
#pragma unroll 2
    for (int c = 0; c < NCH; c++) {
        // prefetch chunk c+1 (LDG latency hides under compute)
        if (c < NCH - 1) {
            int ch_off = (c + 1) * CC * CHSTRIDE;
#pragma unroll
            for (int k = 0; k < NF1; k++)
                r1[k] = (f1_g[k] >= 0) ? f1g[f1_g[k] + ch_off] : 0.f;
#pragma unroll
            for (int k = 0; k < NF0; k++)
                r0[k] = f0g[f0_g[k] + ch_off];
        }

        // compute on buffer c&1
        const float* f1p = ((c & 1) ? f1buf1 : f1buf0) + ty * SW + tx;
        const float* f0p = ((c & 1) ? f0buf1 : f0buf0) + ty * W_ + tx;
#pragma unroll
        for (int cc = 0; cc < CC; cc++) {
            float a = f0p[cc * (TH * W_)];
            const float* fp = f1p + cc * (HALO_H * SW);
#pragma unroll
            for (int i = 0; i < NTAP; i++) {
                if (i < last) acc[i] = fmaf(a, fp[off[i]], acc[i]);
            }
        }

        // store prefetched chunk into the other buffer
        if (c < NCH - 1) {
            float* f1d = ((c & 1) ? f1buf0 : f1buf1);
            float* f0d = ((c & 1) ? f0buf0 : f0buf1);
#pragma unroll
            for (int k = 0; k < NF1; k++) f1d[f1_s[k]] = r1[k];
#pragma unroll
            for (int k = 0; k < NF0; k++) f0d[f0_s[k]] = r0[k];
            __syncthreads();
        }
    }

    // ---- epilogue: masked softmax over taps, split across 4 lanes ----
    const int x = tx;
    const int y = y0 + ty;
    const float scale = 0.125f;

    float m = -1e30f;
#pragma unroll
    for (int i = 0; i < NTAP; i++) {
        int t = g + G_ * i;
        if (t < KT) {
            int dx = t % 7 - R_;
            int dy = t / 7 - R_;
            int gx = x + dx, gy = y + dy;
            if (gx >= 0 && gx < W_ && gy >= 0 && gy < H_)
                m = fmaxf(m, acc[i] * scale);
        }
    }
    m = fmaxf(m, __shfl_xor_sync(0xffffffffu, m, 1));
    m = fmaxf(m, __shfl_xor_sync(0xffffffffu, m, 2));

    float se = 0.f, sx = 0.f, sy = 0.f;
#pragma unroll
    for (int i = 0; i < NTAP; i++) {
        int t = g + G_ * i;
        if (t < KT) {
            int dx = t % 7 - R_;
            int dy = t / 7 - R_;
            int gx = x + dx, gy = y + dy;
            if (gx >= 0 && gx < W_ && gy >= 0 && gy < H_) {
                float e = __expf(acc[i] * scale - m);
                se += e;
                sx += e * (float)dx;
                sy += e * (float)dy;
            }
        }
    }
    se += __shfl_xor_sync(0xffffffffu, se, 1);
    se += __shfl_xor_sync(0xffffffffu, se, 2);
    sx += __shfl_xor_sync(0xffffffffu, sx, 1);
    sx += __shfl_xor_sync(0xffffffffu, sx, 2);
    sy += __shfl_xor_sync(0xffffffffu, sy, 1);
    sy += __shfl_xor_sync(0xffffffffu, sy, 2);

    if (g == 0) {
        float inv = 1.0f / se;
        int ob = ((n_idx * 2) * S_ + s_idx) * P_ + y * W_ + x;
        out[ob]           = sx * inv;
        out[ob + S_ * P_] = sy * inv;
    }
}

extern "C" void kernel_launch(void* const* d_in, const int* in_sizes, int n_in,
                              void* d_out, int out_size) {
    const float* f0 = (const float*)d_in[0];
    const float* f1 = (const float*)d_in[1];
    float* out = (float*)d_out;
    corr_flow_kernel<<<B_ * (H_ / TH), NTHREADS>>>(f0, f1, out);
}